// round 5
// baseline (speedup 1.0000x reference)
#include <cuda_runtime.h>
#include <cstdint>

#define COLS      16384
#define KSEL      64
#define NTHREADS  512
#define GPT       (COLS / (NTHREADS * 4))   // 8 float4-groups per thread
#define CAP       2048

// Monotonic uint key for float ordering (no NaNs expected in data).
__device__ __forceinline__ unsigned fkey(float f) {
    unsigned u = __float_as_uint(f);
    return u ^ ((unsigned)((int)u >> 31) | 0x80000000u);
}

__device__ __forceinline__ float key_to_float(unsigned k) {
    unsigned bits = (k & 0x80000000u) ? (k ^ 0x80000000u) : ~k;
    return __uint_as_float(bits);
}

// Pivot for comparisons; map NaN-encoding keys to +/-inf so float compares
// stay consistent with key-space counting during bisection.
__device__ __forceinline__ float key_to_pivot(unsigned k) {
    float f = key_to_float(k);
    if (f != f) {
        f = (k & 0x80000000u) ? __uint_as_float(0x7F800000u)   // +inf
                              : __uint_as_float(0xFF800000u);  // -inf
    }
    return f;
}

__global__ void __launch_bounds__(NTHREADS, 2)
sparsify_topk_kernel(const float* __restrict__ x, float* __restrict__ out)
{
    __shared__ unsigned s_key[CAP];
    __shared__ int      s_idx[CAP];
    __shared__ int      s_hist[256];
    __shared__ int      s_cnt;
    __shared__ unsigned s_pk, s_lo, s_hi;
    __shared__ unsigned s_selbin;
    __shared__ int      s_need;
    __shared__ int      s_status;

    const int    tid = threadIdx.x;
    const size_t row = blockIdx.x;
    const float4* __restrict__ vin = (const float4*)(x + row * (size_t)COLS);
    float* __restrict__ orow = out + row * (size_t)COLS;

    if (tid == 0) {
        s_pk = fkey(2.4f);      // initial pivot: E[candidates] ~ 135 for N(0,1)
        s_lo = 0u;              // invariant: count(key >= s_lo) >= KSEL
        s_hi = 0xFFFFFFFFu;
    }
    __syncthreads();

    // ---- pivot loop: READ-ONLY candidate collection ----
    for (;;) {
        float pivotf = key_to_pivot(s_pk);
        if (tid == 0) s_cnt = 0;
        __syncthreads();

        // front-batched loads: 8 LDG.128 in flight per warp, no stores at all
        float4 v[GPT];
        #pragma unroll
        for (int it = 0; it < GPT; ++it)
            v[it] = __ldcs(&vin[tid + it * NTHREADS]);

        #pragma unroll
        for (int it = 0; it < GPT; ++it) {
            float m = fmaxf(fmaxf(v[it].x, v[it].y), fmaxf(v[it].z, v[it].w));
            if (m >= pivotf) {
                int base = (tid + it * NTHREADS) * 4;
                if (v[it].x >= pivotf) { int p = atomicAdd(&s_cnt, 1); if (p < CAP) { s_key[p] = fkey(v[it].x); s_idx[p] = base + 0; } }
                if (v[it].y >= pivotf) { int p = atomicAdd(&s_cnt, 1); if (p < CAP) { s_key[p] = fkey(v[it].y); s_idx[p] = base + 1; } }
                if (v[it].z >= pivotf) { int p = atomicAdd(&s_cnt, 1); if (p < CAP) { s_key[p] = fkey(v[it].z); s_idx[p] = base + 2; } }
                if (v[it].w >= pivotf) { int p = atomicAdd(&s_cnt, 1); if (p < CAP) { s_key[p] = fkey(v[it].w); s_idx[p] = base + 3; } }
            }
        }
        __syncthreads();

        int cc = s_cnt;              // uniform: read after barrier
        if (cc >= KSEL && cc <= CAP) break;   // go select exact threshold

        // Bisection retry in key space (essentially never taken on this input)
        if (tid == 0) {
            s_status = 0;
            if (cc < KSEL) {
                s_hi = s_pk;
                unsigned step = (s_pk - s_lo) >> 1;
                if (step == 0) { s_pk = s_lo; s_status = 2; }  // T == s_lo exactly
                else           { s_pk -= step; }
            } else { // cc > CAP
                s_lo = s_pk;
                unsigned step = (s_hi - s_pk) >> 1;
                if (step == 0) { s_status = 2; }               // T == s_pk exactly
                else           { s_pk += step; }
            }
        }
        __syncthreads();
        if (s_status == 2) {
            // pathological fallback: full masked write pass with exact T
            float Tf = key_to_pivot(s_pk);
            float4 vv[GPT];
            #pragma unroll
            for (int it = 0; it < GPT; ++it)
                vv[it] = __ldcs(&vin[tid + it * NTHREADS]);
            float4* vout = (float4*)orow;
            #pragma unroll
            for (int it = 0; it < GPT; ++it) {
                float4 o;
                o.x = (vv[it].x >= Tf) ? vv[it].x : 0.0f;
                o.y = (vv[it].y >= Tf) ? vv[it].y : 0.0f;
                o.z = (vv[it].z >= Tf) ? vv[it].z : 0.0f;
                o.w = (vv[it].w >= Tf) ? vv[it].w : 0.0f;
                vout[tid + it * NTHREADS] = o;
            }
            return;
        }
    }

    // --- exact selection: 4-level radix select, all threads participate ---
    int c = s_cnt;                   // KSEL <= c <= CAP
    unsigned prefix = 0;
    int need = KSEL;
    #pragma unroll
    for (int level = 0; level < 4; ++level) {
        const int shift = 24 - 8 * level;
        if (tid < 256) s_hist[tid] = 0;
        __syncthreads();
        for (int i = tid; i < c; i += NTHREADS) {
            unsigned k = s_key[i];
            bool match = (level == 0) || ((k >> (shift + 8)) == (prefix >> (shift + 8)));
            if (match) atomicAdd(&s_hist[(k >> shift) & 255], 1);
        }
        __syncthreads();
        if (tid < 32) {
            // lane l covers bins [255-8l .. 248-8l] (top-down chunks of 8)
            int base = 255 - 8 * tid;
            int s0 = 0;
            #pragma unroll
            for (int j = 0; j < 8; ++j) s0 += s_hist[base - j];
            // inclusive top-down scan across lanes
            int inc = s0;
            #pragma unroll
            for (int off = 1; off < 32; off <<= 1) {
                int o = __shfl_up_sync(0xFFFFFFFFu, inc, off);
                if (tid >= off) inc += o;
            }
            int excl = inc - s0;   // count in bins strictly above my chunk
            unsigned ball = __ballot_sync(0xFFFFFFFFu, (excl < need) && (need <= inc));
            int lane = __ffs(ball) - 1;
            if (tid == lane) {
                int cum = excl;
                #pragma unroll
                for (int j = 0; j < 8; ++j) {
                    int h = s_hist[base - j];
                    if (cum + h >= need) { s_selbin = (unsigned)(base - j); s_need = need - cum; break; }
                    cum += h;
                }
            }
        }
        __syncthreads();
        prefix |= (s_selbin << shift);
        need = s_need;
    }
    unsigned T = prefix;   // exact key of the KSEL-th largest

    // --- scatter: write only the kept values (>= T, including ties) ---
    for (int i = tid; i < c; i += NTHREADS) {
        unsigned k = s_key[i];
        if (k >= T) orow[s_idx[i]] = key_to_float(k);
    }
}

extern "C" void kernel_launch(void* const* d_in, const int* in_sizes, int n_in,
                              void* d_out, int out_size) {
    const float* x = (const float*)d_in[0];
    float* out = (float*)d_out;
    int rows = in_sizes[0] / COLS;
    cudaMemsetAsync(d_out, 0, (size_t)out_size * sizeof(float), 0);
    sparsify_topk_kernel<<<rows, NTHREADS>>>(x, out);
}

// round 7
// speedup vs baseline: 1.2394x; 1.2394x over previous
#include <cuda_runtime.h>
#include <cstdint>

#define COLS       16384
#define KSEL       64
#define NTHREADS   512
#define CAP        384
#define CHUNK_BYTES 32768
#define CHUNK_F4    2048          // float4 per 32KB chunk
#define ZERO_BYTES  4096
#define NGRID       456           // persistent CTAs (~3/SM)

// ---- dynamic smem layout (bytes) ----
#define OFF_BUF0    0
#define OFF_BUF1    32768
#define OFF_ZERO    65536
#define OFF_KEY     69632         // CAP*4
#define OFF_IDX     71168         // CAP*4
#define OFF_HIST    72704         // 256*4
#define OFF_MBAR0   73728
#define OFF_MBAR1   73736
#define OFF_CNT     73744
#define OFF_SELBIN  73748
#define OFF_NEED    73752
#define OFF_STATUS  73756
#define OFF_PK      73760
#define OFF_LO      73764
#define OFF_HI      73768
#define SMEM_TOTAL  73856

// Monotonic uint key for float ordering.
__device__ __forceinline__ unsigned fkey(float f) {
    unsigned u = __float_as_uint(f);
    return u ^ ((unsigned)((int)u >> 31) | 0x80000000u);
}
__device__ __forceinline__ float key_to_float(unsigned k) {
    unsigned bits = (k & 0x80000000u) ? (k ^ 0x80000000u) : ~k;
    return __uint_as_float(bits);
}
__device__ __forceinline__ float key_to_pivot(unsigned k) {
    float f = key_to_float(k);
    if (f != f) f = (k & 0x80000000u) ? __uint_as_float(0x7F800000u)
                                      : __uint_as_float(0xFF800000u);
    return f;
}

__device__ __forceinline__ uint32_t smem_u32(const void* p) {
    uint32_t a;
    asm("{ .reg .u64 t; cvta.to.shared.u64 t, %1; cvt.u32.u64 %0, t; }"
        : "=r"(a) : "l"(p));
    return a;
}
__device__ __forceinline__ void mbar_init(uint32_t mbar, unsigned cnt) {
    asm volatile("mbarrier.init.shared.b64 [%0], %1;" :: "r"(mbar), "r"(cnt) : "memory");
}
__device__ __forceinline__ void mbar_expect_tx(uint32_t mbar, unsigned bytes) {
    asm volatile("mbarrier.arrive.expect_tx.shared.b64 _, [%0], %1;"
                 :: "r"(mbar), "r"(bytes) : "memory");
}
__device__ __forceinline__ void mbar_wait(uint32_t mbar, unsigned ph) {
    asm volatile(
        "{\n\t.reg .pred P1;\n\t"
        "WAIT_%=:\n\t"
        "mbarrier.try_wait.parity.acquire.cta.shared::cta.b64 P1, [%0], %1, 0x989680;\n\t"
        "@P1 bra.uni DONE_%=;\n\t"
        "bra.uni WAIT_%=;\n\t"
        "DONE_%=:\n\t}"
        :: "r"(mbar), "r"(ph) : "memory");
}
__device__ __forceinline__ void bulk_load(uint32_t dst_smem, const void* src,
                                          unsigned bytes, uint32_t mbar) {
    asm volatile(
        "cp.async.bulk.shared::cluster.global.mbarrier::complete_tx::bytes [%0], [%1], %2, [%3];"
        :: "r"(dst_smem), "l"(src), "r"(bytes), "r"(mbar) : "memory");
}
__device__ __forceinline__ void bulk_store(void* dst, uint32_t src_smem, unsigned bytes) {
    asm volatile("cp.async.bulk.global.shared::cta.bulk_group [%0], [%1], %2;"
                 :: "l"(dst), "r"(src_smem), "r"(bytes) : "memory");
}
__device__ __forceinline__ void bulk_commit() {
    asm volatile("cp.async.bulk.commit_group;" ::: "memory");
}
__device__ __forceinline__ void bulk_wait0() {
    asm volatile("cp.async.bulk.wait_group 0;" ::: "memory");
}

// Pathological fallback: LDG-based key-space bisection (never taken on normal data).
// Returns true if it dense-wrote the row (done); false if candidates are ready.
__device__ __noinline__ bool slow_path(const float* __restrict__ xrow,
                                       float* __restrict__ orow,
                                       unsigned* s_key, int* s_idx,
                                       int* s_cnt, unsigned* s_pk,
                                       unsigned* s_lo, unsigned* s_hi,
                                       int* s_status, int tid)
{
    const float4* vin = (const float4*)xrow;
    if (tid == 0) { *s_pk = fkey(2.4f); *s_lo = 0u; *s_hi = 0xFFFFFFFFu; }
    __syncthreads();
    for (;;) {
        float pivotf = key_to_pivot(*s_pk);
        if (tid == 0) *s_cnt = 0;
        __syncthreads();
        #pragma unroll 1
        for (int it = 0; it < COLS / (NTHREADS * 4); ++it) {
            int g = tid + it * NTHREADS;
            float4 v = vin[g];
            float m = fmaxf(fmaxf(v.x, v.y), fmaxf(v.z, v.w));
            if (m >= pivotf) {
                int base = g * 4;
                if (v.x >= pivotf) { int p = atomicAdd(s_cnt, 1); if (p < CAP) { s_key[p] = fkey(v.x); s_idx[p] = base + 0; } }
                if (v.y >= pivotf) { int p = atomicAdd(s_cnt, 1); if (p < CAP) { s_key[p] = fkey(v.y); s_idx[p] = base + 1; } }
                if (v.z >= pivotf) { int p = atomicAdd(s_cnt, 1); if (p < CAP) { s_key[p] = fkey(v.z); s_idx[p] = base + 2; } }
                if (v.w >= pivotf) { int p = atomicAdd(s_cnt, 1); if (p < CAP) { s_key[p] = fkey(v.w); s_idx[p] = base + 3; } }
            }
        }
        __syncthreads();
        int cc = *s_cnt;
        if (cc >= KSEL && cc <= CAP) return false;   // candidates ready
        if (tid == 0) {
            *s_status = 0;
            if (cc < KSEL) {
                *s_hi = *s_pk;
                unsigned step = (*s_pk - *s_lo) >> 1;
                if (step == 0) { *s_pk = *s_lo; *s_status = 2; }
                else           { *s_pk -= step; }
            } else {
                *s_lo = *s_pk;
                unsigned step = (*s_hi - *s_pk) >> 1;
                if (step == 0) { *s_status = 2; }
                else           { *s_pk += step; }
            }
        }
        __syncthreads();
        if (*s_status == 2) {
            // exact threshold == current pivot: dense masked write
            float Tf = key_to_pivot(*s_pk);
            if (tid == 0) bulk_wait0();   // zeros for this row must land first
            __syncthreads();
            float4* vout = (float4*)orow;
            #pragma unroll 1
            for (int it = 0; it < COLS / (NTHREADS * 4); ++it) {
                int g = tid + it * NTHREADS;
                float4 v = vin[g];
                float4 o;
                o.x = (v.x >= Tf) ? v.x : 0.0f;
                o.y = (v.y >= Tf) ? v.y : 0.0f;
                o.z = (v.z >= Tf) ? v.z : 0.0f;
                o.w = (v.w >= Tf) ? v.w : 0.0f;
                vout[g] = o;
            }
            __syncthreads();
            return true;
        }
    }
}

__global__ void __launch_bounds__(NTHREADS, 3)
sparsify_topk_kernel(const float* __restrict__ x, float* __restrict__ out, int rows)
{
    extern __shared__ __align__(1024) char smem[];
    const int tid = threadIdx.x;

    const float4* buf0 = (const float4*)(smem + OFF_BUF0);
    const float4* buf1 = (const float4*)(smem + OFF_BUF1);
    unsigned* s_key  = (unsigned*)(smem + OFF_KEY);
    int*      s_idx  = (int*)(smem + OFF_IDX);
    int*      s_hist = (int*)(smem + OFF_HIST);
    int*      s_cnt  = (int*)(smem + OFF_CNT);
    unsigned* s_selbin = (unsigned*)(smem + OFF_SELBIN);
    int*      s_need   = (int*)(smem + OFF_NEED);
    int*      s_status = (int*)(smem + OFF_STATUS);
    unsigned* s_pk = (unsigned*)(smem + OFF_PK);
    unsigned* s_lo = (unsigned*)(smem + OFF_LO);
    unsigned* s_hi = (unsigned*)(smem + OFF_HI);

    const uint32_t sbase = smem_u32(smem);
    const uint32_t mb0 = sbase + OFF_MBAR0;
    const uint32_t mb1 = sbase + OFF_MBAR1;
    const uint32_t zsm = sbase + OFF_ZERO;

    // init: mbarriers, zero buffer, counter
    if (tid == 0) { mbar_init(mb0, 1); mbar_init(mb1, 1); *s_cnt = 0; }
    for (int i = tid; i < ZERO_BYTES / 16; i += NTHREADS)
        ((float4*)(smem + OFF_ZERO))[i] = make_float4(0.f, 0.f, 0.f, 0.f);
    asm volatile("fence.proxy.async.shared::cta;" ::: "memory");
    __syncthreads();

    int r = blockIdx.x;
    unsigned ph0 = 0, ph1 = 0;
    if (r < rows && tid == 0) {
        mbar_expect_tx(mb0, CHUNK_BYTES);
        bulk_load(sbase + OFF_BUF0, x + (size_t)r * COLS, CHUNK_BYTES, mb0);
    }

    while (r < rows) {
        const float* xrow = x + (size_t)r * COLS;
        float* orow = out + (size_t)r * COLS;

        if (tid == 0) {
            // async zero-fill of this output row (16 x 4KB)
            #pragma unroll 1
            for (int i = 0; i < COLS * 4 / ZERO_BYTES; ++i)
                bulk_store(orow + i * (ZERO_BYTES / 4), zsm, ZERO_BYTES);
            bulk_commit();
            // load second chunk of this row
            mbar_expect_tx(mb1, CHUNK_BYTES);
            bulk_load(sbase + OFF_BUF1, xrow + CHUNK_F4 * 4, CHUNK_BYTES, mb1);
        }

        // ---- scan chunk 0 ----
        mbar_wait(mb0, ph0); ph0 ^= 1;
        #pragma unroll
        for (int j = 0; j < CHUNK_F4 / NTHREADS; ++j) {
            int g = tid + j * NTHREADS;
            float4 v = buf0[g];
            float m = fmaxf(fmaxf(v.x, v.y), fmaxf(v.z, v.w));
            if (m >= 2.4f) {
                int base = g * 4;
                if (v.x >= 2.4f) { int p = atomicAdd(s_cnt, 1); if (p < CAP) { s_key[p] = fkey(v.x); s_idx[p] = base + 0; } }
                if (v.y >= 2.4f) { int p = atomicAdd(s_cnt, 1); if (p < CAP) { s_key[p] = fkey(v.y); s_idx[p] = base + 1; } }
                if (v.z >= 2.4f) { int p = atomicAdd(s_cnt, 1); if (p < CAP) { s_key[p] = fkey(v.z); s_idx[p] = base + 2; } }
                if (v.w >= 2.4f) { int p = atomicAdd(s_cnt, 1); if (p < CAP) { s_key[p] = fkey(v.w); s_idx[p] = base + 3; } }
            }
        }
        __syncthreads();   // all threads done reading buf0

        // prefetch next row's chunk 0 (keeps DRAM busy through the tail)
        int rn = r + (int)gridDim.x;
        if (rn < rows && tid == 0) {
            mbar_expect_tx(mb0, CHUNK_BYTES);
            bulk_load(sbase + OFF_BUF0, x + (size_t)rn * COLS, CHUNK_BYTES, mb0);
        }

        // ---- scan chunk 1 ----
        mbar_wait(mb1, ph1); ph1 ^= 1;
        #pragma unroll
        for (int j = 0; j < CHUNK_F4 / NTHREADS; ++j) {
            int g = tid + j * NTHREADS;
            float4 v = buf1[g];
            float m = fmaxf(fmaxf(v.x, v.y), fmaxf(v.z, v.w));
            if (m >= 2.4f) {
                int base = (CHUNK_F4 + g) * 4;
                if (v.x >= 2.4f) { int p = atomicAdd(s_cnt, 1); if (p < CAP) { s_key[p] = fkey(v.x); s_idx[p] = base + 0; } }
                if (v.y >= 2.4f) { int p = atomicAdd(s_cnt, 1); if (p < CAP) { s_key[p] = fkey(v.y); s_idx[p] = base + 1; } }
                if (v.z >= 2.4f) { int p = atomicAdd(s_cnt, 1); if (p < CAP) { s_key[p] = fkey(v.z); s_idx[p] = base + 2; } }
                if (v.w >= 2.4f) { int p = atomicAdd(s_cnt, 1); if (p < CAP) { s_key[p] = fkey(v.w); s_idx[p] = base + 3; } }
            }
        }
        __syncthreads();

        int cc = *s_cnt;
        if (cc < KSEL || cc > CAP) {
            if (slow_path(xrow, orow, s_key, s_idx, s_cnt, s_pk, s_lo, s_hi, s_status, tid)) {
                if (tid == 0) *s_cnt = 0;
                __syncthreads();
                r = rn;
                continue;
            }
            cc = *s_cnt;
        }

        // ---- exact selection: 4-level radix select over candidates ----
        unsigned prefix = 0;
        int need = KSEL;
        #pragma unroll
        for (int level = 0; level < 4; ++level) {
            const int shift = 24 - 8 * level;
            if (tid < 256) s_hist[tid] = 0;
            __syncthreads();
            for (int i = tid; i < cc; i += NTHREADS) {
                unsigned k = s_key[i];
                bool match = (level == 0) || ((k >> (shift + 8)) == (prefix >> (shift + 8)));
                if (match) atomicAdd(&s_hist[(k >> shift) & 255], 1);
            }
            __syncthreads();
            if (tid < 32) {
                int base = 255 - 8 * tid;
                int s0 = 0;
                #pragma unroll
                for (int j = 0; j < 8; ++j) s0 += s_hist[base - j];
                int inc = s0;
                #pragma unroll
                for (int off = 1; off < 32; off <<= 1) {
                    int o = __shfl_up_sync(0xFFFFFFFFu, inc, off);
                    if (tid >= off) inc += o;
                }
                int excl = inc - s0;
                unsigned ball = __ballot_sync(0xFFFFFFFFu, (excl < need) && (need <= inc));
                int lane = __ffs(ball) - 1;
                if (tid == lane) {
                    int cum = excl;
                    #pragma unroll
                    for (int j = 0; j < 8; ++j) {
                        int h = s_hist[base - j];
                        if (cum + h >= need) { *s_selbin = (unsigned)(base - j); *s_need = need - cum; break; }
                        cum += h;
                    }
                }
            }
            __syncthreads();
            prefix |= (*s_selbin << shift);
            need = *s_need;
            __syncthreads();
        }
        unsigned T = prefix;

        // zeros for this row must be in GMEM before the scatter overwrites
        if (tid == 0) bulk_wait0();
        __syncthreads();

        for (int i = tid; i < cc; i += NTHREADS) {
            unsigned k = s_key[i];
            if (k >= T) orow[s_idx[i]] = key_to_float(k);
        }

        if (tid == 0) *s_cnt = 0;
        __syncthreads();
        r = rn;
    }
}

extern "C" void kernel_launch(void* const* d_in, const int* in_sizes, int n_in,
                              void* d_out, int out_size) {
    const float* x = (const float*)d_in[0];
    float* out = (float*)d_out;
    int rows = in_sizes[0] / COLS;
    cudaFuncSetAttribute(sparsify_topk_kernel,
                         cudaFuncAttributeMaxDynamicSharedMemorySize, SMEM_TOTAL);
    sparsify_topk_kernel<<<NGRID, NTHREADS, SMEM_TOTAL>>>(x, out, rows);
}